// round 3
// baseline (speedup 1.0000x reference)
#include <cuda_runtime.h>

// SplineFilter: out[b,n,f] = x[b,n,f] * (sum_k basis_k(eig[b,n]) * coeffs[k,f])^2
// Uniform knots linspace(0,2,16), degree 3 -> only 4 nonzero bases per point.
//
// One warp per (b,n) row of 128 channels; lane handles a float4 of channels.
// Coeffs [12][128] staged in shared (6KB), 4 LDS.128 per lane per row.

#define THREADS 256
#define WARPS_PER_BLOCK (THREADS / 32)

__global__ __launch_bounds__(THREADS)
void spline_filter_kernel(const float4* __restrict__ x,
                          const float*  __restrict__ eigs,
                          const float4* __restrict__ coeffs4,  // [12][32] float4
                          float4* __restrict__ out,
                          int nrows)
{
    __shared__ float4 sc[12 * 32];  // [12 bases][128 channels] as float4

    for (int idx = threadIdx.x; idx < 12 * 32; idx += THREADS)
        sc[idx] = coeffs4[idx];
    __syncthreads();

    const int lane = threadIdx.x & 31;
    const int warp = threadIdx.x >> 5;
    const int gw     = blockIdx.x * WARPS_PER_BLOCK + warp;
    const int stride = gridDim.x * WARPS_PER_BLOCK;

    for (int row = gw; row < nrows; row += stride) {
        // --- per-row basis (all lanes redundantly; ~20 flops) ---
        float e = __ldg(&eigs[row]);
        float s = e * 7.5f;                       // 1/h, h = 2/15
        int   i = (int)floorf(s);
        i = max(0, min(i, 14));
        float t  = s - (float)i;
        float u  = 1.0f - t;
        float t2 = t * t;
        float t3 = t2 * t;

        const float k6 = 1.0f / 6.0f;
        float w0 = (u * u * u) * k6;                              // j = i-3
        float w1 = (3.0f * t3 - 6.0f * t2 + 4.0f) * k6;           // j = i-2
        float w2 = (-3.0f * t3 + 3.0f * t2 + 3.0f * t + 1.0f) * k6; // j = i-1
        float w3 = t3 * k6;                                       // j = i

        float wt[4] = {w0, w1, w2, w3};
        const int j0 = i - 3;

        float4 sf = make_float4(0.f, 0.f, 0.f, 0.f);
        #pragma unroll
        for (int m = 0; m < 4; ++m) {
            int   j = j0 + m;
            float w = (j < 0 || j > 11) ? 0.0f : wt[m];
            int  jc = max(0, min(j, 11));
            float4 c = sc[jc * 32 + lane];        // conflict-free: warp reads 512B run
            sf.x = fmaf(w, c.x, sf.x);
            sf.y = fmaf(w, c.y, sf.y);
            sf.z = fmaf(w, c.z, sf.z);
            sf.w = fmaf(w, c.w, sf.w);
        }

        const size_t off = (size_t)row * 32 + lane;
        float4 xv = x[off];
        float4 o;
        o.x = xv.x * (sf.x * sf.x);
        o.y = xv.y * (sf.y * sf.y);
        o.z = xv.z * (sf.z * sf.z);
        o.w = xv.w * (sf.w * sf.w);
        out[off] = o;
    }
}

extern "C" void kernel_launch(void* const* d_in, const int* in_sizes, int n_in,
                              void* d_out, int out_size) {
    const float4* x       = (const float4*)d_in[0];   // eval_x [B,N,128]
    const float*  eigs    = (const float*)d_in[1];    // eval_eigs [B,N]
    const float4* coeffs4 = (const float4*)d_in[2];   // filter_coeffs [12,128]
    float4*       out     = (float4*)d_out;

    const int nrows = in_sizes[1];                    // B*N
    const int blocks = 1184;                          // 8 * 148 SMs, grid-stride
    spline_filter_kernel<<<blocks, THREADS>>>(x, eigs, coeffs4, out, nrows);
}

// round 4
// speedup vs baseline: 1.0020x; 1.0020x over previous
#include <cuda_runtime.h>

// SplineFilter: out[b,n,f] = x[b,n,f] * (sum_k basis_k(eig[b,n]) * coeffs[k,f])^2
// Uniform knots linspace(0,2,16), degree 3 -> only 4 nonzero bases per point.
//
// One warp per (b,n) row of 128 channels; lane handles a float4 of channels.
// Coeffs [12][128] staged in shared (6KB), 4 LDS.128 per lane per row.

#define THREADS 256
#define WARPS_PER_BLOCK (THREADS / 32)

__global__ __launch_bounds__(THREADS)
void spline_filter_kernel(const float4* __restrict__ x,
                          const float*  __restrict__ eigs,
                          const float4* __restrict__ coeffs4,  // [12][32] float4
                          float4* __restrict__ out,
                          int nrows)
{
    __shared__ float4 sc[12 * 32];  // [12 bases][128 channels] as float4

    for (int idx = threadIdx.x; idx < 12 * 32; idx += THREADS)
        sc[idx] = coeffs4[idx];
    __syncthreads();

    const int lane = threadIdx.x & 31;
    const int warp = threadIdx.x >> 5;
    const int gw     = blockIdx.x * WARPS_PER_BLOCK + warp;
    const int stride = gridDim.x * WARPS_PER_BLOCK;

    for (int row = gw; row < nrows; row += stride) {
        // --- per-row basis (all lanes redundantly; ~20 flops) ---
        float e = __ldg(&eigs[row]);
        float s = e * 7.5f;                       // 1/h, h = 2/15
        int   i = (int)floorf(s);
        i = max(0, min(i, 14));
        float t  = s - (float)i;
        float u  = 1.0f - t;
        float t2 = t * t;
        float t3 = t2 * t;

        const float k6 = 1.0f / 6.0f;
        float w0 = (u * u * u) * k6;                              // j = i-3
        float w1 = (3.0f * t3 - 6.0f * t2 + 4.0f) * k6;           // j = i-2
        float w2 = (-3.0f * t3 + 3.0f * t2 + 3.0f * t + 1.0f) * k6; // j = i-1
        float w3 = t3 * k6;                                       // j = i

        float wt[4] = {w0, w1, w2, w3};
        const int j0 = i - 3;

        float4 sf = make_float4(0.f, 0.f, 0.f, 0.f);
        #pragma unroll
        for (int m = 0; m < 4; ++m) {
            int   j = j0 + m;
            float w = (j < 0 || j > 11) ? 0.0f : wt[m];
            int  jc = max(0, min(j, 11));
            float4 c = sc[jc * 32 + lane];        // conflict-free: warp reads 512B run
            sf.x = fmaf(w, c.x, sf.x);
            sf.y = fmaf(w, c.y, sf.y);
            sf.z = fmaf(w, c.z, sf.z);
            sf.w = fmaf(w, c.w, sf.w);
        }

        const size_t off = (size_t)row * 32 + lane;
        float4 xv = x[off];
        float4 o;
        o.x = xv.x * (sf.x * sf.x);
        o.y = xv.y * (sf.y * sf.y);
        o.z = xv.z * (sf.z * sf.z);
        o.w = xv.w * (sf.w * sf.w);
        out[off] = o;
    }
}

extern "C" void kernel_launch(void* const* d_in, const int* in_sizes, int n_in,
                              void* d_out, int out_size) {
    const float4* x       = (const float4*)d_in[0];   // eval_x [B,N,128]
    const float*  eigs    = (const float*)d_in[1];    // eval_eigs [B,N]
    const float4* coeffs4 = (const float4*)d_in[2];   // filter_coeffs [12,128]
    float4*       out     = (float4*)d_out;

    const int nrows = in_sizes[1];                    // B*N
    const int blocks = 1184;                          // 8 * 148 SMs, grid-stride
    spline_filter_kernel<<<blocks, THREADS>>>(x, eigs, coeffs4, out, nrows);
}